// round 13
// baseline (speedup 1.0000x reference)
#include <cuda_runtime.h>
#include <cuda_fp16.h>
#include <math.h>

#define NN   50000
#define EE   1600000
#define DIN_ 128
#define SLOTS 128            // padded per-node edge capacity (deg ~Poisson(32))

// ------------------------- device scratch (no allocs) -------------------------
__device__ float  g_h[NN * 128];        // fp32 transformed features (edge gather)
__device__ float  g_x[NN * 128];
__device__ float  g_as[NN * 8];         // logits pre-scaled by log2(e)
__device__ float  g_ad[NN * 8];
__device__ int    g_cursor[NN];
__device__ int    g_esrc[NN * SLOTS];   // padded bucket CSR (25.6 MB)

// ------------------------- padded-CSR build ------------------------------------
#define SC_GRID 1563   // 1563*256*4 >= EE

__global__ void k_init2(int* cursor, int* esrc) {
    int i = blockIdx.x * 256 + threadIdx.x;
    if (i < NN) {
        cursor[i] = i * SLOTS + 1;
        esrc[i * SLOTS] = i;
    }
}

__global__ void k_scatter(const int* __restrict__ A, int* cursor, int* esrc) {
    const int S = SC_GRID * 256;
    int t0 = blockIdx.x * 256 + threadIdx.x;
#pragma unroll
    for (int q = 0; q < 4; q++) {
        int idx = t0 + q * S;
        if (idx < EE) {
            int s = A[idx];
            int d = A[EE + idx];
            int pos = atomicAdd(&cursor[d], 1);
            esrc[pos] = s;
        }
    }
}

// ------------------------- tensor-core GEMM + fused attn logits ----------------
__device__ __forceinline__ unsigned f2tf32(float f) {
    unsigned u;
    asm("cvt.rna.tf32.f32 %0, %1;" : "=r"(u) : "f"(f));
    return u;
}
__device__ __forceinline__ float ex2f(float x) {
    float r;
    asm("ex2.approx.f32 %0, %1;" : "=f"(r) : "f"(x));
    return r;
}

#define LOG2E 1.4426950408889634f

template <int COLS>
__global__ __launch_bounds__(256) void gemm_tc(const float* __restrict__ X,
                                               const float* __restrict__ W,
                                               const float* __restrict__ a_s,
                                               const float* __restrict__ a_d,
                                               float* __restrict__ Hout,
                                               float* __restrict__ ASRC,
                                               float* __restrict__ ADST) {
    constexpr int BM = 128, BK = 32;
    constexpr int WM = (COLS == 128) ? 4 : 8;
    constexpr int MF = BM / (WM * 16);
    constexpr int NF = 8;
    constexpr int APAD = BK + 4;
    constexpr int WPAD = COLS + 8;
    constexpr int H = COLS / 16;

    __shared__ float As[BM][APAD];
    __shared__ float Ws[BK][WPAD];
    __shared__ float as_sm[COLS], ad_sm[COLS];

    const int t = threadIdx.x;
    const int lane = t & 31;
    const int wid = t >> 5;
    const int wm = wid % WM;
    const int wn = wid / WM;
    const int row0 = blockIdx.x * BM;
    const int g = lane >> 2;
    const int q4 = lane & 3;

    // logits pre-scaled by log2(e): exp(x) == ex2(scaled dot)
    if (t < COLS) { as_sm[t] = a_s[t] * LOG2E; ad_sm[t] = a_d[t] * LOG2E; }

    float acc[MF][NF][4];
#pragma unroll
    for (int mf = 0; mf < MF; mf++)
#pragma unroll
        for (int nf = 0; nf < NF; nf++)
#pragma unroll
            for (int i = 0; i < 4; i++) acc[mf][nf][i] = 0.f;

#pragma unroll 1
    for (int kt = 0; kt < DIN_; kt += BK) {
        {
            constexpr int NV = BK * COLS / 4 / 256;
            const float4* Wg = reinterpret_cast<const float4*>(W + kt * COLS);
#pragma unroll
            for (int i = 0; i < NV; i++) {
                int qq = t + i * 256;
                int r = qq / (COLS / 4), c = qq % (COLS / 4);
                float4 v = Wg[qq];
                uint4 u = make_uint4(f2tf32(v.x), f2tf32(v.y), f2tf32(v.z), f2tf32(v.w));
                *reinterpret_cast<uint4*>(&Ws[r][c * 4]) = u;
            }
        }
        {
#pragma unroll
            for (int i = 0; i < 4; i++) {
                int qq = t + i * 256;
                int r = qq >> 3, c = qq & 7;
                int gr = row0 + r;
                float4 v = make_float4(0.f, 0.f, 0.f, 0.f);
                if (gr < NN)
                    v = reinterpret_cast<const float4*>(X + gr * DIN_ + kt)[c];
                uint4 u = make_uint4(f2tf32(v.x), f2tf32(v.y), f2tf32(v.z), f2tf32(v.w));
                *reinterpret_cast<uint4*>(&As[r][c * 4]) = u;
            }
        }
        __syncthreads();
#pragma unroll
        for (int k8 = 0; k8 < BK; k8 += 8) {
            unsigned a[MF][4];
#pragma unroll
            for (int mf = 0; mf < MF; mf++) {
                int r = wm * (MF * 16) + mf * 16 + g;
                a[mf][0] = __float_as_uint(As[r][k8 + q4]);
                a[mf][1] = __float_as_uint(As[r + 8][k8 + q4]);
                a[mf][2] = __float_as_uint(As[r][k8 + q4 + 4]);
                a[mf][3] = __float_as_uint(As[r + 8][k8 + q4 + 4]);
            }
            unsigned b[NF][2];
#pragma unroll
            for (int nf = 0; nf < NF; nf++) {
                int c = wn * 64 + nf * 8 + g;
                b[nf][0] = __float_as_uint(Ws[k8 + q4][c]);
                b[nf][1] = __float_as_uint(Ws[k8 + q4 + 4][c]);
            }
#pragma unroll
            for (int mf = 0; mf < MF; mf++)
#pragma unroll
                for (int nf = 0; nf < NF; nf++)
                    asm volatile(
                        "mma.sync.aligned.m16n8k8.row.col.f32.tf32.tf32.f32 "
                        "{%0,%1,%2,%3}, {%4,%5,%6,%7}, {%8,%9}, {%0,%1,%2,%3};"
                        : "+f"(acc[mf][nf][0]), "+f"(acc[mf][nf][1]),
                          "+f"(acc[mf][nf][2]), "+f"(acc[mf][nf][3])
                        : "r"(a[mf][0]), "r"(a[mf][1]), "r"(a[mf][2]), "r"(a[mf][3]),
                          "r"(b[nf][0]), "r"(b[nf][1]));
        }
        __syncthreads();
    }

#pragma unroll
    for (int mf = 0; mf < MF; mf++) {
        int r = row0 + wm * (MF * 16) + mf * 16 + g;
        float psA[4] = {0, 0, 0, 0}, pdA[4] = {0, 0, 0, 0};
        float psB[4] = {0, 0, 0, 0}, pdB[4] = {0, 0, 0, 0};
#pragma unroll
        for (int nf = 0; nf < NF; nf++) {
            int c = wn * 64 + nf * 8 + 2 * q4;
            int hl = nf >> 1;
            float sa0 = as_sm[c], sa1 = as_sm[c + 1];
            float da0 = ad_sm[c], da1 = ad_sm[c + 1];
            psA[hl] += acc[mf][nf][0] * sa0 + acc[mf][nf][1] * sa1;
            pdA[hl] += acc[mf][nf][0] * da0 + acc[mf][nf][1] * da1;
            psB[hl] += acc[mf][nf][2] * sa0 + acc[mf][nf][3] * sa1;
            pdB[hl] += acc[mf][nf][2] * da0 + acc[mf][nf][3] * da1;
            if (r < NN)
                *reinterpret_cast<float2*>(&Hout[r * COLS + c]) =
                    make_float2(acc[mf][nf][0], acc[mf][nf][1]);
            if (r + 8 < NN)
                *reinterpret_cast<float2*>(&Hout[(r + 8) * COLS + c]) =
                    make_float2(acc[mf][nf][2], acc[mf][nf][3]);
        }
#pragma unroll
        for (int hl = 0; hl < 4; hl++) {
            psA[hl] += __shfl_xor_sync(~0u, psA[hl], 1);
            psA[hl] += __shfl_xor_sync(~0u, psA[hl], 2);
            pdA[hl] += __shfl_xor_sync(~0u, pdA[hl], 1);
            pdA[hl] += __shfl_xor_sync(~0u, pdA[hl], 2);
            psB[hl] += __shfl_xor_sync(~0u, psB[hl], 1);
            psB[hl] += __shfl_xor_sync(~0u, psB[hl], 2);
            pdB[hl] += __shfl_xor_sync(~0u, pdB[hl], 1);
            pdB[hl] += __shfl_xor_sync(~0u, pdB[hl], 2);
        }
        if (q4 == 0) {
            if (r < NN) {
                *reinterpret_cast<float4*>(&ASRC[r * H + wn * 4]) =
                    make_float4(psA[0], psA[1], psA[2], psA[3]);
                *reinterpret_cast<float4*>(&ADST[r * H + wn * 4]) =
                    make_float4(pdA[0], pdA[1], pdA[2], pdA[3]);
            }
            if (r + 8 < NN) {
                *reinterpret_cast<float4*>(&ASRC[(r + 8) * H + wn * 4]) =
                    make_float4(psB[0], psB[1], psB[2], psB[3]);
                *reinterpret_cast<float4*>(&ADST[(r + 8) * H + wn * 4]) =
                    make_float4(pdB[0], pdB[1], pdB[2], pdB[3]);
            }
        }
    }
}

// ------------- aggregation, HF=128: half-warp per edge, 2 edges/iter -----------
// fp32 gather (no cvt): lane j reads features j*8..j*8+7 as two float4s.
template <bool RELU>
__global__ __launch_bounds__(256) void agg128_k(const float* __restrict__ Hf,
                                                const float* __restrict__ ASRC,
                                                const float* __restrict__ ADST,
                                                const int* __restrict__ esrc,
                                                const int* __restrict__ ends,
                                                const float* __restrict__ bias,
                                                float* __restrict__ out) {
    int n = blockIdx.x * 8 + (threadIdx.x >> 5);
    if (n >= NN) return;
    const int lane = threadIdx.x & 31;
    const int sub = lane >> 4;
    const int j = lane & 15;
    const int head = j >> 1;

    const float adn = ADST[n * 8 + head];
    float s = 0.f;
    float acc[8];
#pragma unroll
    for (int v = 0; v < 8; v++) acc[v] = 0.f;

    const int e0 = n * SLOTS;
    const int end = ends[n];

#pragma unroll 2
    for (int e = e0; e < end; e += 2) {
        int ee = e + sub;
        int src = esrc[min(ee, end - 1)];
        float ea = ASRC[src * 8 + head];
        const float4* hp = reinterpret_cast<const float4*>(Hf) + src * 32 + j * 2;
        float4 u0 = hp[0];
        float4 u1 = hp[1];
        float ev = ea + adn;                 // already in log2 domain
        ev = ev > 0.f ? ev : 0.2f * ev;      // leaky commutes with positive scale
        float p = ex2f(ev);
        p = (ee < end) ? p : 0.f;
        s += p;
        acc[0] = fmaf(p, u0.x, acc[0]); acc[1] = fmaf(p, u0.y, acc[1]);
        acc[2] = fmaf(p, u0.z, acc[2]); acc[3] = fmaf(p, u0.w, acc[3]);
        acc[4] = fmaf(p, u1.x, acc[4]); acc[5] = fmaf(p, u1.y, acc[5]);
        acc[6] = fmaf(p, u1.z, acc[6]); acc[7] = fmaf(p, u1.w, acc[7]);
    }

    // combine the two half-warps
    s += __shfl_xor_sync(~0u, s, 16);
#pragma unroll
    for (int v = 0; v < 8; v++) acc[v] += __shfl_xor_sync(~0u, acc[v], 16);

    const float inv = 1.f / (s + 1e-16f);
    if (sub == 0) {
        float4 o0, o1;
        o0.x = acc[0] * inv + bias[j * 8 + 0];
        o0.y = acc[1] * inv + bias[j * 8 + 1];
        o0.z = acc[2] * inv + bias[j * 8 + 2];
        o0.w = acc[3] * inv + bias[j * 8 + 3];
        o1.x = acc[4] * inv + bias[j * 8 + 4];
        o1.y = acc[5] * inv + bias[j * 8 + 5];
        o1.z = acc[6] * inv + bias[j * 8 + 6];
        o1.w = acc[7] * inv + bias[j * 8 + 7];
        if (RELU) {
            o0.x = fmaxf(o0.x, 0.f); o0.y = fmaxf(o0.y, 0.f);
            o0.z = fmaxf(o0.z, 0.f); o0.w = fmaxf(o0.w, 0.f);
            o1.x = fmaxf(o1.x, 0.f); o1.y = fmaxf(o1.y, 0.f);
            o1.z = fmaxf(o1.z, 0.f); o1.w = fmaxf(o1.w, 0.f);
        }
        reinterpret_cast<float4*>(out)[n * 32 + j * 2] = o0;
        reinterpret_cast<float4*>(out)[n * 32 + j * 2 + 1] = o1;
    }
}

// -------- aggregation, HF=64, mean over 4 heads: quarter-warp, 4 edges/iter ----
__global__ __launch_bounds__(256) void agg64_mean_k(const float* __restrict__ Hf,
                                                    const float* __restrict__ ASRC,
                                                    const float* __restrict__ ADST,
                                                    const int* __restrict__ esrc,
                                                    const int* __restrict__ ends,
                                                    const float* __restrict__ bias,
                                                    float* __restrict__ out) {
    int n = blockIdx.x * 8 + (threadIdx.x >> 5);
    if (n >= NN) return;
    const int lane = threadIdx.x & 31;
    const int sub = lane >> 3;
    const int j = lane & 7;
    const int head = j >> 1;

    const float adn = ADST[n * 4 + head];
    float s = 0.f;
    float acc[8];
#pragma unroll
    for (int v = 0; v < 8; v++) acc[v] = 0.f;

    const int e0 = n * SLOTS;
    const int end = ends[n];

#pragma unroll 2
    for (int e = e0; e < end; e += 4) {
        int ee = e + sub;
        int src = esrc[min(ee, end - 1)];
        float ea = ASRC[src * 4 + head];
        const float4* hp = reinterpret_cast<const float4*>(Hf) + src * 16 + j * 2;
        float4 u0 = hp[0];
        float4 u1 = hp[1];
        float ev = ea + adn;
        ev = ev > 0.f ? ev : 0.2f * ev;
        float p = ex2f(ev);
        p = (ee < end) ? p : 0.f;
        s += p;
        acc[0] = fmaf(p, u0.x, acc[0]); acc[1] = fmaf(p, u0.y, acc[1]);
        acc[2] = fmaf(p, u0.z, acc[2]); acc[3] = fmaf(p, u0.w, acc[3]);
        acc[4] = fmaf(p, u1.x, acc[4]); acc[5] = fmaf(p, u1.y, acc[5]);
        acc[6] = fmaf(p, u1.z, acc[6]); acc[7] = fmaf(p, u1.w, acc[7]);
    }

    // combine the four sub-groups (lane bits 3,4)
    s += __shfl_xor_sync(~0u, s, 8);
    s += __shfl_xor_sync(~0u, s, 16);
#pragma unroll
    for (int v = 0; v < 8; v++) {
        acc[v] += __shfl_xor_sync(~0u, acc[v], 8);
        acc[v] += __shfl_xor_sync(~0u, acc[v], 16);
    }
    // normalize per head, then mean over heads (lane bits 1,2 flip head bits)
    const float inv = 1.f / (s + 1e-16f);
#pragma unroll
    for (int v = 0; v < 8; v++) {
        acc[v] *= inv;
        acc[v] += __shfl_xor_sync(~0u, acc[v], 2);
        acc[v] += __shfl_xor_sync(~0u, acc[v], 4);
    }
    if (lane < 2) {
        int fi = lane * 8;
        float4 o0, o1;
        o0.x = 0.25f * acc[0] + bias[fi + 0];
        o0.y = 0.25f * acc[1] + bias[fi + 1];
        o0.z = 0.25f * acc[2] + bias[fi + 2];
        o0.w = 0.25f * acc[3] + bias[fi + 3];
        o1.x = 0.25f * acc[4] + bias[fi + 4];
        o1.y = 0.25f * acc[5] + bias[fi + 5];
        o1.z = 0.25f * acc[6] + bias[fi + 6];
        o1.w = 0.25f * acc[7] + bias[fi + 7];
        reinterpret_cast<float4*>(out)[n * 4 + lane * 2] = o0;
        reinterpret_cast<float4*>(out)[n * 4 + lane * 2 + 1] = o1;
    }
}

// ------------------------- launcher -------------------------------------------
extern "C" void kernel_launch(void* const* d_in, const int* in_sizes, int n_in,
                              void* d_out, int out_size) {
    const float* X   = (const float*)d_in[0];
    const int*   A   = (const int*)d_in[1];
    const float* W1  = (const float*)d_in[2];
    const float* as1 = (const float*)d_in[3];
    const float* ad1 = (const float*)d_in[4];
    const float* b1  = (const float*)d_in[5];
    const float* W2  = (const float*)d_in[6];
    const float* as2 = (const float*)d_in[7];
    const float* ad2 = (const float*)d_in[8];
    const float* b2  = (const float*)d_in[9];
    const float* W3  = (const float*)d_in[10];
    const float* as3 = (const float*)d_in[11];
    const float* ad3 = (const float*)d_in[12];
    const float* b3  = (const float*)d_in[13];
    float* out = (float*)d_out;

    void* p;
    float *h, *x, *asb, *adb;
    int *cursor, *esrc;
    cudaGetSymbolAddress(&p, g_h);      h = (float*)p;
    cudaGetSymbolAddress(&p, g_x);      x = (float*)p;
    cudaGetSymbolAddress(&p, g_as);     asb = (float*)p;
    cudaGetSymbolAddress(&p, g_ad);     adb = (float*)p;
    cudaGetSymbolAddress(&p, g_cursor); cursor = (int*)p;
    cudaGetSymbolAddress(&p, g_esrc);   esrc = (int*)p;

    static cudaStream_t s_side = nullptr;
    static cudaEvent_t  s_ev0 = nullptr, s_ev1 = nullptr;
    if (s_side == nullptr) {
        cudaStreamCreateWithFlags(&s_side, cudaStreamNonBlocking);
        cudaEventCreateWithFlags(&s_ev0, cudaEventDisableTiming);
        cudaEventCreateWithFlags(&s_ev1, cudaEventDisableTiming);
    }

    const int GB = (NN + 127) / 128;    // 391
    const int AB = (NN + 7) / 8;

    // ---- fork: padded-CSR build on side stream (2 kernels total) ----
    cudaEventRecord(s_ev0, 0);
    cudaStreamWaitEvent(s_side, s_ev0, 0);
    k_init2<<<(NN + 255) / 256, 256, 0, s_side>>>(cursor, esrc);
    k_scatter<<<SC_GRID, 256, 0, s_side>>>(A, cursor, esrc);
    cudaEventRecord(s_ev1, s_side);

    // ---- main stream: layer-1 GEMM overlaps the CSR build ----
    gemm_tc<128><<<GB, 256>>>(X, W1, as1, ad1, h, asb, adb);
    cudaStreamWaitEvent(0, s_ev1, 0);

    agg128_k<true><<<AB, 256>>>(h, asb, adb, esrc, cursor, b1, x);
    gemm_tc<128><<<GB, 256>>>(x, W2, as2, ad2, h, asb, adb);
    agg128_k<true><<<AB, 256>>>(h, asb, adb, esrc, cursor, b2, x);
    gemm_tc<64><<<GB, 256>>>(x, W3, as3, ad3, h, asb, adb);
    agg64_mean_k<<<AB, 256>>>(h, asb, adb, esrc, cursor, b3, out);
}

// round 14
// speedup vs baseline: 1.2487x; 1.2487x over previous
#include <cuda_runtime.h>
#include <cuda_fp16.h>
#include <math.h>

#define NN   50000
#define EE   1600000
#define DIN_ 128
#define SLOTS 128            // padded per-node edge capacity (deg ~Poisson(32))

// ------------------------- device scratch (no allocs) -------------------------
__device__ __half g_hh[NN * 128];       // fp16 transformed features (edge gather)
__device__ float  g_x[NN * 128];
__device__ float  g_as[NN * 8];         // logits pre-scaled by log2(e)
__device__ float  g_ad[NN * 8];
__device__ int    g_cursor[NN];
__device__ int    g_esrc[NN * SLOTS];   // padded bucket CSR (25.6 MB)

// ------------------------- padded-CSR build ------------------------------------
#define SC_GRID 1563   // 1563*256*4 >= EE

__global__ void k_init2(int* cursor, int* esrc) {
    int i = blockIdx.x * 256 + threadIdx.x;
    if (i < NN) {
        cursor[i] = i * SLOTS + 1;
        esrc[i * SLOTS] = i;
    }
}

__global__ void k_scatter(const int* __restrict__ A, int* cursor, int* esrc) {
    const int S = SC_GRID * 256;
    int t0 = blockIdx.x * 256 + threadIdx.x;
#pragma unroll
    for (int q = 0; q < 4; q++) {
        int idx = t0 + q * S;
        if (idx < EE) {
            int s = A[idx];
            int d = A[EE + idx];
            int pos = atomicAdd(&cursor[d], 1);
            esrc[pos] = s;
        }
    }
}

// ------------------------- helpers ---------------------------------------------
__device__ __forceinline__ unsigned f2tf32(float f) {
    unsigned u;
    asm("cvt.rna.tf32.f32 %0, %1;" : "=r"(u) : "f"(f));
    return u;
}
__device__ __forceinline__ float ex2f(float x) {
    float r;
    asm("ex2.approx.f32 %0, %1;" : "=f"(r) : "f"(x));
    return r;
}
#define LOG2E 1.4426950408889634f

// ------------------------- tensor-core GEMM + fused attn logits ----------------
template <int COLS>
__global__ __launch_bounds__(256) void gemm_tc(const float* __restrict__ X,
                                               const float* __restrict__ W,
                                               const float* __restrict__ a_s,
                                               const float* __restrict__ a_d,
                                               __half* __restrict__ Hh,
                                               float* __restrict__ ASRC,
                                               float* __restrict__ ADST) {
    constexpr int BM = 128, BK = 32;
    constexpr int WM = (COLS == 128) ? 4 : 8;
    constexpr int MF = BM / (WM * 16);
    constexpr int NF = 8;
    constexpr int APAD = BK + 4;
    constexpr int WPAD = COLS + 8;
    constexpr int H = COLS / 16;

    __shared__ float As[BM][APAD];
    __shared__ float Ws[BK][WPAD];
    __shared__ float as_sm[COLS], ad_sm[COLS];

    const int t = threadIdx.x;
    const int lane = t & 31;
    const int wid = t >> 5;
    const int wm = wid % WM;
    const int wn = wid / WM;
    const int row0 = blockIdx.x * BM;
    const int g = lane >> 2;
    const int q4 = lane & 3;

    // logits pre-scaled by log2(e): exp(x) == ex2(scaled dot)
    if (t < COLS) { as_sm[t] = a_s[t] * LOG2E; ad_sm[t] = a_d[t] * LOG2E; }

    float acc[MF][NF][4];
#pragma unroll
    for (int mf = 0; mf < MF; mf++)
#pragma unroll
        for (int nf = 0; nf < NF; nf++)
#pragma unroll
            for (int i = 0; i < 4; i++) acc[mf][nf][i] = 0.f;

#pragma unroll 1
    for (int kt = 0; kt < DIN_; kt += BK) {
        {
            constexpr int NV = BK * COLS / 4 / 256;
            const float4* Wg = reinterpret_cast<const float4*>(W + kt * COLS);
#pragma unroll
            for (int i = 0; i < NV; i++) {
                int qq = t + i * 256;
                int r = qq / (COLS / 4), c = qq % (COLS / 4);
                float4 v = Wg[qq];
                uint4 u = make_uint4(f2tf32(v.x), f2tf32(v.y), f2tf32(v.z), f2tf32(v.w));
                *reinterpret_cast<uint4*>(&Ws[r][c * 4]) = u;
            }
        }
        {
#pragma unroll
            for (int i = 0; i < 4; i++) {
                int qq = t + i * 256;
                int r = qq >> 3, c = qq & 7;
                int gr = row0 + r;
                float4 v = make_float4(0.f, 0.f, 0.f, 0.f);
                if (gr < NN)
                    v = reinterpret_cast<const float4*>(X + gr * DIN_ + kt)[c];
                uint4 u = make_uint4(f2tf32(v.x), f2tf32(v.y), f2tf32(v.z), f2tf32(v.w));
                *reinterpret_cast<uint4*>(&As[r][c * 4]) = u;
            }
        }
        __syncthreads();
#pragma unroll
        for (int k8 = 0; k8 < BK; k8 += 8) {
            unsigned a[MF][4];
#pragma unroll
            for (int mf = 0; mf < MF; mf++) {
                int r = wm * (MF * 16) + mf * 16 + g;
                a[mf][0] = __float_as_uint(As[r][k8 + q4]);
                a[mf][1] = __float_as_uint(As[r + 8][k8 + q4]);
                a[mf][2] = __float_as_uint(As[r][k8 + q4 + 4]);
                a[mf][3] = __float_as_uint(As[r + 8][k8 + q4 + 4]);
            }
            unsigned b[NF][2];
#pragma unroll
            for (int nf = 0; nf < NF; nf++) {
                int c = wn * 64 + nf * 8 + g;
                b[nf][0] = __float_as_uint(Ws[k8 + q4][c]);
                b[nf][1] = __float_as_uint(Ws[k8 + q4 + 4][c]);
            }
#pragma unroll
            for (int mf = 0; mf < MF; mf++)
#pragma unroll
                for (int nf = 0; nf < NF; nf++)
                    asm volatile(
                        "mma.sync.aligned.m16n8k8.row.col.f32.tf32.tf32.f32 "
                        "{%0,%1,%2,%3}, {%4,%5,%6,%7}, {%8,%9}, {%0,%1,%2,%3};"
                        : "+f"(acc[mf][nf][0]), "+f"(acc[mf][nf][1]),
                          "+f"(acc[mf][nf][2]), "+f"(acc[mf][nf][3])
                        : "r"(a[mf][0]), "r"(a[mf][1]), "r"(a[mf][2]), "r"(a[mf][3]),
                          "r"(b[nf][0]), "r"(b[nf][1]));
        }
        __syncthreads();
    }

#pragma unroll
    for (int mf = 0; mf < MF; mf++) {
        int r = row0 + wm * (MF * 16) + mf * 16 + g;
        float psA[4] = {0, 0, 0, 0}, pdA[4] = {0, 0, 0, 0};
        float psB[4] = {0, 0, 0, 0}, pdB[4] = {0, 0, 0, 0};
#pragma unroll
        for (int nf = 0; nf < NF; nf++) {
            int c = wn * 64 + nf * 8 + 2 * q4;
            int hl = nf >> 1;
            float sa0 = as_sm[c], sa1 = as_sm[c + 1];
            float da0 = ad_sm[c], da1 = ad_sm[c + 1];
            psA[hl] += acc[mf][nf][0] * sa0 + acc[mf][nf][1] * sa1;
            pdA[hl] += acc[mf][nf][0] * da0 + acc[mf][nf][1] * da1;
            psB[hl] += acc[mf][nf][2] * sa0 + acc[mf][nf][3] * sa1;
            pdB[hl] += acc[mf][nf][2] * da0 + acc[mf][nf][3] * da1;
            if (r < NN)
                *reinterpret_cast<__half2*>(&Hh[r * COLS + c]) =
                    __floats2half2_rn(acc[mf][nf][0], acc[mf][nf][1]);
            if (r + 8 < NN)
                *reinterpret_cast<__half2*>(&Hh[(r + 8) * COLS + c]) =
                    __floats2half2_rn(acc[mf][nf][2], acc[mf][nf][3]);
        }
#pragma unroll
        for (int hl = 0; hl < 4; hl++) {
            psA[hl] += __shfl_xor_sync(~0u, psA[hl], 1);
            psA[hl] += __shfl_xor_sync(~0u, psA[hl], 2);
            pdA[hl] += __shfl_xor_sync(~0u, pdA[hl], 1);
            pdA[hl] += __shfl_xor_sync(~0u, pdA[hl], 2);
            psB[hl] += __shfl_xor_sync(~0u, psB[hl], 1);
            psB[hl] += __shfl_xor_sync(~0u, psB[hl], 2);
            pdB[hl] += __shfl_xor_sync(~0u, pdB[hl], 1);
            pdB[hl] += __shfl_xor_sync(~0u, pdB[hl], 2);
        }
        if (q4 == 0) {
            if (r < NN) {
                *reinterpret_cast<float4*>(&ASRC[r * H + wn * 4]) =
                    make_float4(psA[0], psA[1], psA[2], psA[3]);
                *reinterpret_cast<float4*>(&ADST[r * H + wn * 4]) =
                    make_float4(pdA[0], pdA[1], pdA[2], pdA[3]);
            }
            if (r + 8 < NN) {
                *reinterpret_cast<float4*>(&ASRC[(r + 8) * H + wn * 4]) =
                    make_float4(psB[0], psB[1], psB[2], psB[3]);
                *reinterpret_cast<float4*>(&ADST[(r + 8) * H + wn * 4]) =
                    make_float4(pdB[0], pdB[1], pdB[2], pdB[3]);
            }
        }
    }
}

// ------------- aggregation, HF=128: half-warp per edge, 2 edges/iter -----------
// R11 layout (fp16 gather, 16 lanes sweep one 256B row); exp via ex2 on
// log2e-prescaled logits.
template <bool RELU>
__global__ __launch_bounds__(256) void agg128_k(const __half* __restrict__ Hh,
                                                const float* __restrict__ ASRC,
                                                const float* __restrict__ ADST,
                                                const int* __restrict__ esrc,
                                                const int* __restrict__ ends,
                                                const float* __restrict__ bias,
                                                float* __restrict__ out) {
    int n = blockIdx.x * 8 + (threadIdx.x >> 5);
    if (n >= NN) return;
    const int lane = threadIdx.x & 31;
    const int sub = lane >> 4;
    const int j = lane & 15;
    const int head = j >> 1;

    const float adn = ADST[n * 8 + head];
    float s = 0.f;
    float acc[8];
#pragma unroll
    for (int v = 0; v < 8; v++) acc[v] = 0.f;

    const int e0 = n * SLOTS;
    const int end = ends[n];

#pragma unroll 2
    for (int e = e0; e < end; e += 2) {
        int ee = e + sub;
        int src = esrc[min(ee, end - 1)];
        float ea = ASRC[src * 8 + head];
        uint4 u = reinterpret_cast<const uint4*>(Hh)[src * 16 + j];
        float ev = ea + adn;                 // log2 domain
        ev = ev > 0.f ? ev : 0.2f * ev;      // leaky commutes with positive scale
        float p = ex2f(ev);
        p = (ee < end) ? p : 0.f;
        s += p;
        float2 f0 = __half22float2(*reinterpret_cast<__half2*>(&u.x));
        float2 f1 = __half22float2(*reinterpret_cast<__half2*>(&u.y));
        float2 f2 = __half22float2(*reinterpret_cast<__half2*>(&u.z));
        float2 f3 = __half22float2(*reinterpret_cast<__half2*>(&u.w));
        acc[0] = fmaf(p, f0.x, acc[0]); acc[1] = fmaf(p, f0.y, acc[1]);
        acc[2] = fmaf(p, f1.x, acc[2]); acc[3] = fmaf(p, f1.y, acc[3]);
        acc[4] = fmaf(p, f2.x, acc[4]); acc[5] = fmaf(p, f2.y, acc[5]);
        acc[6] = fmaf(p, f3.x, acc[6]); acc[7] = fmaf(p, f3.y, acc[7]);
    }

    // combine the two half-warps
    s += __shfl_xor_sync(~0u, s, 16);
#pragma unroll
    for (int v = 0; v < 8; v++) acc[v] += __shfl_xor_sync(~0u, acc[v], 16);

    const float inv = 1.f / (s + 1e-16f);
    if (sub == 0) {
        float4 o0, o1;
        o0.x = acc[0] * inv + bias[j * 8 + 0];
        o0.y = acc[1] * inv + bias[j * 8 + 1];
        o0.z = acc[2] * inv + bias[j * 8 + 2];
        o0.w = acc[3] * inv + bias[j * 8 + 3];
        o1.x = acc[4] * inv + bias[j * 8 + 4];
        o1.y = acc[5] * inv + bias[j * 8 + 5];
        o1.z = acc[6] * inv + bias[j * 8 + 6];
        o1.w = acc[7] * inv + bias[j * 8 + 7];
        if (RELU) {
            o0.x = fmaxf(o0.x, 0.f); o0.y = fmaxf(o0.y, 0.f);
            o0.z = fmaxf(o0.z, 0.f); o0.w = fmaxf(o0.w, 0.f);
            o1.x = fmaxf(o1.x, 0.f); o1.y = fmaxf(o1.y, 0.f);
            o1.z = fmaxf(o1.z, 0.f); o1.w = fmaxf(o1.w, 0.f);
        }
        reinterpret_cast<float4*>(out)[n * 32 + j * 2] = o0;
        reinterpret_cast<float4*>(out)[n * 32 + j * 2 + 1] = o1;
    }
}

// -------- aggregation, HF=64, mean over 4 heads: quarter-warp, 4 edges/iter ----
__global__ __launch_bounds__(256) void agg64_mean_k(const __half* __restrict__ Hh,
                                                    const float* __restrict__ ASRC,
                                                    const float* __restrict__ ADST,
                                                    const int* __restrict__ esrc,
                                                    const int* __restrict__ ends,
                                                    const float* __restrict__ bias,
                                                    float* __restrict__ out) {
    int n = blockIdx.x * 8 + (threadIdx.x >> 5);
    if (n >= NN) return;
    const int lane = threadIdx.x & 31;
    const int sub = lane >> 3;
    const int j = lane & 7;
    const int head = j >> 1;

    const float adn = ADST[n * 4 + head];
    float s = 0.f;
    float acc[8];
#pragma unroll
    for (int v = 0; v < 8; v++) acc[v] = 0.f;

    const int e0 = n * SLOTS;
    const int end = ends[n];

#pragma unroll 2
    for (int e = e0; e < end; e += 4) {
        int ee = e + sub;
        int src = esrc[min(ee, end - 1)];
        float ea = ASRC[src * 4 + head];
        uint4 u = reinterpret_cast<const uint4*>(Hh)[src * 8 + j];
        float ev = ea + adn;
        ev = ev > 0.f ? ev : 0.2f * ev;
        float p = ex2f(ev);
        p = (ee < end) ? p : 0.f;
        s += p;
        float2 f0 = __half22float2(*reinterpret_cast<__half2*>(&u.x));
        float2 f1 = __half22float2(*reinterpret_cast<__half2*>(&u.y));
        float2 f2 = __half22float2(*reinterpret_cast<__half2*>(&u.z));
        float2 f3 = __half22float2(*reinterpret_cast<__half2*>(&u.w));
        acc[0] = fmaf(p, f0.x, acc[0]); acc[1] = fmaf(p, f0.y, acc[1]);
        acc[2] = fmaf(p, f1.x, acc[2]); acc[3] = fmaf(p, f1.y, acc[3]);
        acc[4] = fmaf(p, f2.x, acc[4]); acc[5] = fmaf(p, f2.y, acc[5]);
        acc[6] = fmaf(p, f3.x, acc[6]); acc[7] = fmaf(p, f3.y, acc[7]);
    }

    // combine the four sub-groups (lane bits 3,4)
    s += __shfl_xor_sync(~0u, s, 8);
    s += __shfl_xor_sync(~0u, s, 16);
#pragma unroll
    for (int v = 0; v < 8; v++) {
        acc[v] += __shfl_xor_sync(~0u, acc[v], 8);
        acc[v] += __shfl_xor_sync(~0u, acc[v], 16);
    }
    // normalize per head, then mean over heads (lane bits 1,2 flip head bits)
    const float inv = 1.f / (s + 1e-16f);
#pragma unroll
    for (int v = 0; v < 8; v++) {
        acc[v] *= inv;
        acc[v] += __shfl_xor_sync(~0u, acc[v], 2);
        acc[v] += __shfl_xor_sync(~0u, acc[v], 4);
    }
    if (lane < 2) {
        int fi = lane * 8;
        float4 o0, o1;
        o0.x = 0.25f * acc[0] + bias[fi + 0];
        o0.y = 0.25f * acc[1] + bias[fi + 1];
        o0.z = 0.25f * acc[2] + bias[fi + 2];
        o0.w = 0.25f * acc[3] + bias[fi + 3];
        o1.x = 0.25f * acc[4] + bias[fi + 4];
        o1.y = 0.25f * acc[5] + bias[fi + 5];
        o1.z = 0.25f * acc[6] + bias[fi + 6];
        o1.w = 0.25f * acc[7] + bias[fi + 7];
        reinterpret_cast<float4*>(out)[n * 4 + lane * 2] = o0;
        reinterpret_cast<float4*>(out)[n * 4 + lane * 2 + 1] = o1;
    }
}

// ------------------------- launcher -------------------------------------------
extern "C" void kernel_launch(void* const* d_in, const int* in_sizes, int n_in,
                              void* d_out, int out_size) {
    const float* X   = (const float*)d_in[0];
    const int*   A   = (const int*)d_in[1];
    const float* W1  = (const float*)d_in[2];
    const float* as1 = (const float*)d_in[3];
    const float* ad1 = (const float*)d_in[4];
    const float* b1  = (const float*)d_in[5];
    const float* W2  = (const float*)d_in[6];
    const float* as2 = (const float*)d_in[7];
    const float* ad2 = (const float*)d_in[8];
    const float* b2  = (const float*)d_in[9];
    const float* W3  = (const float*)d_in[10];
    const float* as3 = (const float*)d_in[11];
    const float* ad3 = (const float*)d_in[12];
    const float* b3  = (const float*)d_in[13];
    float* out = (float*)d_out;

    void* p;
    float *x, *asb, *adb;
    __half* hh;
    int *cursor, *esrc;
    cudaGetSymbolAddress(&p, g_hh);     hh = (__half*)p;
    cudaGetSymbolAddress(&p, g_x);      x = (float*)p;
    cudaGetSymbolAddress(&p, g_as);     asb = (float*)p;
    cudaGetSymbolAddress(&p, g_ad);     adb = (float*)p;
    cudaGetSymbolAddress(&p, g_cursor); cursor = (int*)p;
    cudaGetSymbolAddress(&p, g_esrc);   esrc = (int*)p;

    static cudaStream_t s_side = nullptr;
    static cudaEvent_t  s_ev0 = nullptr, s_ev1 = nullptr;
    if (s_side == nullptr) {
        cudaStreamCreateWithFlags(&s_side, cudaStreamNonBlocking);
        cudaEventCreateWithFlags(&s_ev0, cudaEventDisableTiming);
        cudaEventCreateWithFlags(&s_ev1, cudaEventDisableTiming);
    }

    const int GB = (NN + 127) / 128;    // 391
    const int AB = (NN + 7) / 8;

    // ---- fork: padded-CSR build on side stream (2 kernels total) ----
    cudaEventRecord(s_ev0, 0);
    cudaStreamWaitEvent(s_side, s_ev0, 0);
    k_init2<<<(NN + 255) / 256, 256, 0, s_side>>>(cursor, esrc);
    k_scatter<<<SC_GRID, 256, 0, s_side>>>(A, cursor, esrc);
    cudaEventRecord(s_ev1, s_side);

    // ---- main stream: layer-1 GEMM overlaps the CSR build ----
    gemm_tc<128><<<GB, 256>>>(X, W1, as1, ad1, hh, asb, adb);
    cudaStreamWaitEvent(0, s_ev1, 0);

    agg128_k<true><<<AB, 256>>>(hh, asb, adb, esrc, cursor, b1, x);
    gemm_tc<128><<<GB, 256>>>(x, W2, as2, ad2, hh, asb, adb);
    agg128_k<true><<<AB, 256>>>(hh, asb, adb, esrc, cursor, b2, x);
    gemm_tc<64><<<GB, 256>>>(x, W3, as3, ad3, hh, asb, adb);
    agg64_mean_k<<<AB, 256>>>(hh, asb, adb, esrc, cursor, b3, out);
}

// round 15
// speedup vs baseline: 1.2958x; 1.0378x over previous
#include <cuda_runtime.h>
#include <cuda_fp16.h>
#include <math.h>

#define NN   50000
#define EE   1600000
#define DIN_ 128
#define SLOTS 128            // padded per-node edge capacity (deg ~Poisson(32))

// ------------------------- device scratch (no allocs) -------------------------
__device__ __half g_hh[NN * 128];       // fp16 transformed features (edge gather)
__device__ float  g_x[NN * 128];
__device__ float  g_as[NN * 8];         // logits pre-scaled by log2(e)
__device__ float  g_ad[NN * 8];
__device__ int    g_cursor[NN];
__device__ int    g_esrc[NN * SLOTS];   // padded bucket CSR (25.6 MB)

// ------------------------- padded-CSR build ------------------------------------
#define SC_GRID 1563   // 1563*256*4 >= EE

__global__ void k_init2(int* cursor, int* esrc) {
    int i = blockIdx.x * 256 + threadIdx.x;
    if (i < NN) {
        cursor[i] = i * SLOTS + 1;
        esrc[i * SLOTS] = i;
    }
}

__global__ void k_scatter(const int* __restrict__ A, int* cursor, int* esrc) {
    const int S = SC_GRID * 256;
    int t0 = blockIdx.x * 256 + threadIdx.x;
#pragma unroll
    for (int q = 0; q < 4; q++) {
        int idx = t0 + q * S;
        if (idx < EE) {
            int s = A[idx];
            int d = A[EE + idx];
            int pos = atomicAdd(&cursor[d], 1);
            esrc[pos] = s;
        }
    }
}

// ------------------------- helpers ---------------------------------------------
__device__ __forceinline__ unsigned f2tf32(float f) {
    unsigned u;
    asm("cvt.rna.tf32.f32 %0, %1;" : "=r"(u) : "f"(f));
    return u;
}
__device__ __forceinline__ float ex2f(float x) {
    float r;
    asm("ex2.approx.f32 %0, %1;" : "=f"(r) : "f"(x));
    return r;
}
#define LOG2E 1.4426950408889634f

// ------------------------- tensor-core GEMM + fused attn logits ----------------
template <int COLS>
__global__ __launch_bounds__(256) void gemm_tc(const float* __restrict__ X,
                                               const float* __restrict__ W,
                                               const float* __restrict__ a_s,
                                               const float* __restrict__ a_d,
                                               __half* __restrict__ Hh,
                                               float* __restrict__ ASRC,
                                               float* __restrict__ ADST) {
    constexpr int BM = 128, BK = 32;
    constexpr int WM = (COLS == 128) ? 4 : 8;
    constexpr int MF = BM / (WM * 16);
    constexpr int NF = 8;
    constexpr int APAD = BK + 4;
    constexpr int WPAD = COLS + 8;
    constexpr int H = COLS / 16;

    __shared__ float As[BM][APAD];
    __shared__ float Ws[BK][WPAD];
    __shared__ float as_sm[COLS], ad_sm[COLS];

    const int t = threadIdx.x;
    const int lane = t & 31;
    const int wid = t >> 5;
    const int wm = wid % WM;
    const int wn = wid / WM;
    const int row0 = blockIdx.x * BM;
    const int g = lane >> 2;
    const int q4 = lane & 3;

    // logits pre-scaled by log2(e): exp(x) == ex2(scaled dot)
    if (t < COLS) { as_sm[t] = a_s[t] * LOG2E; ad_sm[t] = a_d[t] * LOG2E; }

    float acc[MF][NF][4];
#pragma unroll
    for (int mf = 0; mf < MF; mf++)
#pragma unroll
        for (int nf = 0; nf < NF; nf++)
#pragma unroll
            for (int i = 0; i < 4; i++) acc[mf][nf][i] = 0.f;

#pragma unroll 1
    for (int kt = 0; kt < DIN_; kt += BK) {
        {
            constexpr int NV = BK * COLS / 4 / 256;
            const float4* Wg = reinterpret_cast<const float4*>(W + kt * COLS);
#pragma unroll
            for (int i = 0; i < NV; i++) {
                int qq = t + i * 256;
                int r = qq / (COLS / 4), c = qq % (COLS / 4);
                float4 v = Wg[qq];
                uint4 u = make_uint4(f2tf32(v.x), f2tf32(v.y), f2tf32(v.z), f2tf32(v.w));
                *reinterpret_cast<uint4*>(&Ws[r][c * 4]) = u;
            }
        }
        {
#pragma unroll
            for (int i = 0; i < 4; i++) {
                int qq = t + i * 256;
                int r = qq >> 3, c = qq & 7;
                int gr = row0 + r;
                float4 v = make_float4(0.f, 0.f, 0.f, 0.f);
                if (gr < NN)
                    v = reinterpret_cast<const float4*>(X + gr * DIN_ + kt)[c];
                uint4 u = make_uint4(f2tf32(v.x), f2tf32(v.y), f2tf32(v.z), f2tf32(v.w));
                *reinterpret_cast<uint4*>(&As[r][c * 4]) = u;
            }
        }
        __syncthreads();
#pragma unroll
        for (int k8 = 0; k8 < BK; k8 += 8) {
            unsigned a[MF][4];
#pragma unroll
            for (int mf = 0; mf < MF; mf++) {
                int r = wm * (MF * 16) + mf * 16 + g;
                a[mf][0] = __float_as_uint(As[r][k8 + q4]);
                a[mf][1] = __float_as_uint(As[r + 8][k8 + q4]);
                a[mf][2] = __float_as_uint(As[r][k8 + q4 + 4]);
                a[mf][3] = __float_as_uint(As[r + 8][k8 + q4 + 4]);
            }
            unsigned b[NF][2];
#pragma unroll
            for (int nf = 0; nf < NF; nf++) {
                int c = wn * 64 + nf * 8 + g;
                b[nf][0] = __float_as_uint(Ws[k8 + q4][c]);
                b[nf][1] = __float_as_uint(Ws[k8 + q4 + 4][c]);
            }
#pragma unroll
            for (int mf = 0; mf < MF; mf++)
#pragma unroll
                for (int nf = 0; nf < NF; nf++)
                    asm volatile(
                        "mma.sync.aligned.m16n8k8.row.col.f32.tf32.tf32.f32 "
                        "{%0,%1,%2,%3}, {%4,%5,%6,%7}, {%8,%9}, {%0,%1,%2,%3};"
                        : "+f"(acc[mf][nf][0]), "+f"(acc[mf][nf][1]),
                          "+f"(acc[mf][nf][2]), "+f"(acc[mf][nf][3])
                        : "r"(a[mf][0]), "r"(a[mf][1]), "r"(a[mf][2]), "r"(a[mf][3]),
                          "r"(b[nf][0]), "r"(b[nf][1]));
        }
        __syncthreads();
    }

#pragma unroll
    for (int mf = 0; mf < MF; mf++) {
        int r = row0 + wm * (MF * 16) + mf * 16 + g;
        float psA[4] = {0, 0, 0, 0}, pdA[4] = {0, 0, 0, 0};
        float psB[4] = {0, 0, 0, 0}, pdB[4] = {0, 0, 0, 0};
#pragma unroll
        for (int nf = 0; nf < NF; nf++) {
            int c = wn * 64 + nf * 8 + 2 * q4;
            int hl = nf >> 1;
            float sa0 = as_sm[c], sa1 = as_sm[c + 1];
            float da0 = ad_sm[c], da1 = ad_sm[c + 1];
            psA[hl] += acc[mf][nf][0] * sa0 + acc[mf][nf][1] * sa1;
            pdA[hl] += acc[mf][nf][0] * da0 + acc[mf][nf][1] * da1;
            psB[hl] += acc[mf][nf][2] * sa0 + acc[mf][nf][3] * sa1;
            pdB[hl] += acc[mf][nf][2] * da0 + acc[mf][nf][3] * da1;
            if (r < NN)
                *reinterpret_cast<__half2*>(&Hh[r * COLS + c]) =
                    __floats2half2_rn(acc[mf][nf][0], acc[mf][nf][1]);
            if (r + 8 < NN)
                *reinterpret_cast<__half2*>(&Hh[(r + 8) * COLS + c]) =
                    __floats2half2_rn(acc[mf][nf][2], acc[mf][nf][3]);
        }
#pragma unroll
        for (int hl = 0; hl < 4; hl++) {
            psA[hl] += __shfl_xor_sync(~0u, psA[hl], 1);
            psA[hl] += __shfl_xor_sync(~0u, psA[hl], 2);
            pdA[hl] += __shfl_xor_sync(~0u, pdA[hl], 1);
            pdA[hl] += __shfl_xor_sync(~0u, pdA[hl], 2);
            psB[hl] += __shfl_xor_sync(~0u, psB[hl], 1);
            psB[hl] += __shfl_xor_sync(~0u, psB[hl], 2);
            pdB[hl] += __shfl_xor_sync(~0u, pdB[hl], 1);
            pdB[hl] += __shfl_xor_sync(~0u, pdB[hl], 2);
        }
        if (q4 == 0) {
            if (r < NN) {
                *reinterpret_cast<float4*>(&ASRC[r * H + wn * 4]) =
                    make_float4(psA[0], psA[1], psA[2], psA[3]);
                *reinterpret_cast<float4*>(&ADST[r * H + wn * 4]) =
                    make_float4(pdA[0], pdA[1], pdA[2], pdA[3]);
            }
            if (r + 8 < NN) {
                *reinterpret_cast<float4*>(&ASRC[(r + 8) * H + wn * 4]) =
                    make_float4(psB[0], psB[1], psB[2], psB[3]);
                *reinterpret_cast<float4*>(&ADST[(r + 8) * H + wn * 4]) =
                    make_float4(pdB[0], pdB[1], pdB[2], pdB[3]);
            }
        }
    }
}

// ------------- aggregation, HF=128: half-warp per edge, 2 edges/iter -----------
// Feature accumulation in fp16 (HFMA2, no cvt) flushed to fp32 every 8 edges.
template <bool RELU>
__global__ __launch_bounds__(256) void agg128_k(const __half* __restrict__ Hh,
                                                const float* __restrict__ ASRC,
                                                const float* __restrict__ ADST,
                                                const int* __restrict__ esrc,
                                                const int* __restrict__ ends,
                                                const float* __restrict__ bias,
                                                float* __restrict__ out) {
    int n = blockIdx.x * 8 + (threadIdx.x >> 5);
    if (n >= NN) return;
    const int lane = threadIdx.x & 31;
    const int sub = lane >> 4;
    const int j = lane & 15;
    const int head = j >> 1;

    const float adn = ADST[n * 8 + head];
    float s = 0.f;
    float facc[8];
#pragma unroll
    for (int v = 0; v < 8; v++) facc[v] = 0.f;

    const int e0 = n * SLOTS;
    const int end = ends[n];

#pragma unroll 1
    for (int e = e0; e < end; e += 8) {       // 8-edge chunk (4 iters of 2)
        __half2 hacc[4];
        hacc[0] = hacc[1] = hacc[2] = hacc[3] = __float2half2_rn(0.f);
#pragma unroll
        for (int k = 0; k < 4; k++) {
            int ee = e + 2 * k + sub;
            int src = esrc[min(ee, end - 1)];
            float ea = ASRC[src * 8 + head];
            uint4 u = reinterpret_cast<const uint4*>(Hh)[src * 16 + j];
            float ev = ea + adn;                 // log2 domain
            ev = ev > 0.f ? ev : 0.2f * ev;      // leaky commutes with positive scale
            float p = ex2f(ev);
            p = (ee < end) ? p : 0.f;
            s += p;
            __half2 ph = __float2half2_rn(p);
            hacc[0] = __hfma2(ph, *reinterpret_cast<__half2*>(&u.x), hacc[0]);
            hacc[1] = __hfma2(ph, *reinterpret_cast<__half2*>(&u.y), hacc[1]);
            hacc[2] = __hfma2(ph, *reinterpret_cast<__half2*>(&u.z), hacc[2]);
            hacc[3] = __hfma2(ph, *reinterpret_cast<__half2*>(&u.w), hacc[3]);
        }
#pragma unroll
        for (int v = 0; v < 4; v++) {
            float2 f = __half22float2(hacc[v]);
            facc[2 * v] += f.x;
            facc[2 * v + 1] += f.y;
        }
    }

    // combine the two half-warps
    s += __shfl_xor_sync(~0u, s, 16);
#pragma unroll
    for (int v = 0; v < 8; v++) facc[v] += __shfl_xor_sync(~0u, facc[v], 16);

    const float inv = 1.f / (s + 1e-16f);
    if (sub == 0) {
        float4 o0, o1;
        o0.x = facc[0] * inv + bias[j * 8 + 0];
        o0.y = facc[1] * inv + bias[j * 8 + 1];
        o0.z = facc[2] * inv + bias[j * 8 + 2];
        o0.w = facc[3] * inv + bias[j * 8 + 3];
        o1.x = facc[4] * inv + bias[j * 8 + 4];
        o1.y = facc[5] * inv + bias[j * 8 + 5];
        o1.z = facc[6] * inv + bias[j * 8 + 6];
        o1.w = facc[7] * inv + bias[j * 8 + 7];
        if (RELU) {
            o0.x = fmaxf(o0.x, 0.f); o0.y = fmaxf(o0.y, 0.f);
            o0.z = fmaxf(o0.z, 0.f); o0.w = fmaxf(o0.w, 0.f);
            o1.x = fmaxf(o1.x, 0.f); o1.y = fmaxf(o1.y, 0.f);
            o1.z = fmaxf(o1.z, 0.f); o1.w = fmaxf(o1.w, 0.f);
        }
        reinterpret_cast<float4*>(out)[n * 32 + j * 2] = o0;
        reinterpret_cast<float4*>(out)[n * 32 + j * 2 + 1] = o1;
    }
}

// -------- aggregation, HF=64, mean over 4 heads: quarter-warp, 4 edges/iter ----
__global__ __launch_bounds__(256) void agg64_mean_k(const __half* __restrict__ Hh,
                                                    const float* __restrict__ ASRC,
                                                    const float* __restrict__ ADST,
                                                    const int* __restrict__ esrc,
                                                    const int* __restrict__ ends,
                                                    const float* __restrict__ bias,
                                                    float* __restrict__ out) {
    int n = blockIdx.x * 8 + (threadIdx.x >> 5);
    if (n >= NN) return;
    const int lane = threadIdx.x & 31;
    const int sub = lane >> 3;
    const int j = lane & 7;
    const int head = j >> 1;

    const float adn = ADST[n * 4 + head];
    float s = 0.f;
    float facc[8];
#pragma unroll
    for (int v = 0; v < 8; v++) facc[v] = 0.f;

    const int e0 = n * SLOTS;
    const int end = ends[n];

#pragma unroll 1
    for (int e = e0; e < end; e += 8) {       // 8-edge chunk (2 iters of 4)
        __half2 hacc[4];
        hacc[0] = hacc[1] = hacc[2] = hacc[3] = __float2half2_rn(0.f);
#pragma unroll
        for (int k = 0; k < 2; k++) {
            int ee = e + 4 * k + sub;
            int src = esrc[min(ee, end - 1)];
            float ea = ASRC[src * 4 + head];
            uint4 u = reinterpret_cast<const uint4*>(Hh)[src * 8 + j];
            float ev = ea + adn;
            ev = ev > 0.f ? ev : 0.2f * ev;
            float p = ex2f(ev);
            p = (ee < end) ? p : 0.f;
            s += p;
            __half2 ph = __float2half2_rn(p);
            hacc[0] = __hfma2(ph, *reinterpret_cast<__half2*>(&u.x), hacc[0]);
            hacc[1] = __hfma2(ph, *reinterpret_cast<__half2*>(&u.y), hacc[1]);
            hacc[2] = __hfma2(ph, *reinterpret_cast<__half2*>(&u.z), hacc[2]);
            hacc[3] = __hfma2(ph, *reinterpret_cast<__half2*>(&u.w), hacc[3]);
        }
#pragma unroll
        for (int v = 0; v < 4; v++) {
            float2 f = __half22float2(hacc[v]);
            facc[2 * v] += f.x;
            facc[2 * v + 1] += f.y;
        }
    }

    // combine the four sub-groups (lane bits 3,4)
    s += __shfl_xor_sync(~0u, s, 8);
    s += __shfl_xor_sync(~0u, s, 16);
#pragma unroll
    for (int v = 0; v < 8; v++) {
        facc[v] += __shfl_xor_sync(~0u, facc[v], 8);
        facc[v] += __shfl_xor_sync(~0u, facc[v], 16);
    }
    // normalize per head, then mean over heads (lane bits 1,2 flip head bits)
    const float inv = 1.f / (s + 1e-16f);
#pragma unroll
    for (int v = 0; v < 8; v++) {
        facc[v] *= inv;
        facc[v] += __shfl_xor_sync(~0u, facc[v], 2);
        facc[v] += __shfl_xor_sync(~0u, facc[v], 4);
    }
    if (lane < 2) {
        int fi = lane * 8;
        float4 o0, o1;
        o0.x = 0.25f * facc[0] + bias[fi + 0];
        o0.y = 0.25f * facc[1] + bias[fi + 1];
        o0.z = 0.25f * facc[2] + bias[fi + 2];
        o0.w = 0.25f * facc[3] + bias[fi + 3];
        o1.x = 0.25f * facc[4] + bias[fi + 4];
        o1.y = 0.25f * facc[5] + bias[fi + 5];
        o1.z = 0.25f * facc[6] + bias[fi + 6];
        o1.w = 0.25f * facc[7] + bias[fi + 7];
        reinterpret_cast<float4*>(out)[n * 4 + lane * 2] = o0;
        reinterpret_cast<float4*>(out)[n * 4 + lane * 2 + 1] = o1;
    }
}

// ------------------------- launcher -------------------------------------------
extern "C" void kernel_launch(void* const* d_in, const int* in_sizes, int n_in,
                              void* d_out, int out_size) {
    const float* X   = (const float*)d_in[0];
    const int*   A   = (const int*)d_in[1];
    const float* W1  = (const float*)d_in[2];
    const float* as1 = (const float*)d_in[3];
    const float* ad1 = (const float*)d_in[4];
    const float* b1  = (const float*)d_in[5];
    const float* W2  = (const float*)d_in[6];
    const float* as2 = (const float*)d_in[7];
    const float* ad2 = (const float*)d_in[8];
    const float* b2  = (const float*)d_in[9];
    const float* W3  = (const float*)d_in[10];
    const float* as3 = (const float*)d_in[11];
    const float* ad3 = (const float*)d_in[12];
    const float* b3  = (const float*)d_in[13];
    float* out = (float*)d_out;

    void* p;
    float *x, *asb, *adb;
    __half* hh;
    int *cursor, *esrc;
    cudaGetSymbolAddress(&p, g_hh);     hh = (__half*)p;
    cudaGetSymbolAddress(&p, g_x);      x = (float*)p;
    cudaGetSymbolAddress(&p, g_as);     asb = (float*)p;
    cudaGetSymbolAddress(&p, g_ad);     adb = (float*)p;
    cudaGetSymbolAddress(&p, g_cursor); cursor = (int*)p;
    cudaGetSymbolAddress(&p, g_esrc);   esrc = (int*)p;

    static cudaStream_t s_side = nullptr;
    static cudaEvent_t  s_ev0 = nullptr, s_ev1 = nullptr;
    if (s_side == nullptr) {
        cudaStreamCreateWithFlags(&s_side, cudaStreamNonBlocking);
        cudaEventCreateWithFlags(&s_ev0, cudaEventDisableTiming);
        cudaEventCreateWithFlags(&s_ev1, cudaEventDisableTiming);
    }

    const int GB = (NN + 127) / 128;    // 391
    const int AB = (NN + 7) / 8;

    // ---- fork: padded-CSR build on side stream (2 kernels total) ----
    cudaEventRecord(s_ev0, 0);
    cudaStreamWaitEvent(s_side, s_ev0, 0);
    k_init2<<<(NN + 255) / 256, 256, 0, s_side>>>(cursor, esrc);
    k_scatter<<<SC_GRID, 256, 0, s_side>>>(A, cursor, esrc);
    cudaEventRecord(s_ev1, s_side);

    // ---- main stream: layer-1 GEMM overlaps the CSR build ----
    gemm_tc<128><<<GB, 256>>>(X, W1, as1, ad1, hh, asb, adb);
    cudaStreamWaitEvent(0, s_ev1, 0);

    agg128_k<true><<<AB, 256>>>(hh, asb, adb, esrc, cursor, b1, x);
    gemm_tc<128><<<GB, 256>>>(x, W2, as2, ad2, hh, asb, adb);
    agg128_k<true><<<AB, 256>>>(hh, asb, adb, esrc, cursor, b2, x);
    gemm_tc<64><<<GB, 256>>>(x, W3, as3, ad3, hh, asb, adb);
    agg64_mean_k<<<AB, 256>>>(hh, asb, adb, esrc, cursor, b3, out);
}